// round 16
// baseline (speedup 1.0000x reference)
#include <cuda_runtime.h>
#include <cuda_bf16.h>
#include <cstdint>

// ---------------------------------------------------------------------------
// GINConv: out = relu((x + segment_sum(x[src], dst)) @ W1 + b1) @ W2 + b2
// N=50000, E=640000, D=128, fp32, edge_index int32. 2 launches.
//
//   K1: graph_kernel (sms blocks x 1024 thr, software grid barriers):
//         P1 hist   - deg histogram + per-edge rank (+ weight split, base 0)
//         P2 scan   - per-chunk scan -> g_exc; chunk bases via atomics
//         P3 fill   - csr[g_exc[dst] + g_base[dst>>10] + rank[e]] = src
//         P4 gather - agg = x + sum x[csr] (warp/node, 4-way); resets g_deg
//   K2: mlp - PERSISTENT HMMA bf16x3, 256 thr / 255 regs, 4(m)x2(n) warps
//       (512 thr spills: R7. Gather must NOT move into this kernel: R10.)
// ---------------------------------------------------------------------------

#define DIM    128
#define MAX_N  50000
#define MAX_E  640000
#define TILE_M 128
#define PA     136                       // padded pitch (elems), 272B rows
#define TBYTES (128 * PA * 2)            // 34816 B per bf16 tile

__device__ float g_agg[MAX_N * DIM];

__device__ int g_deg[MAX_N];             // zero-init at load; gather resets
__device__ int g_exc[MAX_N];
__device__ int g_base[64];
__device__ int g_rank[MAX_E];
__device__ int g_csr[MAX_E];

// software grid barrier state (zero-init; count self-resets, gen monotonic)
__device__ int g_bar_count;
__device__ int g_bar_gen;

// W^T hi/lo tiles, [n][k] row-major, pitch PA
__device__ __align__(16) __nv_bfloat16 g_w1h[128 * PA];
__device__ __align__(16) __nv_bfloat16 g_w1l[128 * PA];
__device__ __align__(16) __nv_bfloat16 g_w2h[128 * PA];
__device__ __align__(16) __nv_bfloat16 g_w2l[128 * PA];

__device__ __forceinline__ uint32_t smem_u32(const void* p) {
    uint32_t a;
    asm("{ .reg .u64 t; cvta.to.shared.u64 t, %1; cvt.u32.u64 %0, t; }"
        : "=r"(a) : "l"(p));
    return a;
}
__device__ __forceinline__ void ldmx4(uint32_t addr, uint32_t r[4]) {
    asm volatile("ldmatrix.sync.aligned.m8n8.x4.shared.b16 {%0,%1,%2,%3}, [%4];"
                 : "=r"(r[0]), "=r"(r[1]), "=r"(r[2]), "=r"(r[3]) : "r"(addr));
}
__device__ __forceinline__ void mma16816(float c[4], const uint32_t a[4],
                                         uint32_t b0, uint32_t b1) {
    asm volatile("mma.sync.aligned.m16n8k16.row.col.f32.bf16.bf16.f32 "
                 "{%0,%1,%2,%3}, {%4,%5,%6,%7}, {%8,%9}, {%0,%1,%2,%3};"
                 : "+f"(c[0]), "+f"(c[1]), "+f"(c[2]), "+f"(c[3])
                 : "r"(a[0]), "r"(a[1]), "r"(a[2]), "r"(a[3]), "r"(b0), "r"(b1));
}
__device__ __forceinline__ void bf16_split(float a, __nv_bfloat16& h, __nv_bfloat16& l) {
    h = __float2bfloat16_rn(a);
    l = __float2bfloat16_rn(a - __bfloat162float(h));
}
__device__ __forceinline__ void f4add(float4& a, const float4 b) {
    a.x += b.x; a.y += b.y; a.z += b.z; a.w += b.w;
}

// grid barrier: all nb blocks arrive; generation 'target' releases.
__device__ __forceinline__ void grid_barrier(int nb, int target) {
    __syncthreads();
    if (threadIdx.x == 0) {
        __threadfence();
        int t = atomicAdd(&g_bar_count, 1);
        if (t == nb - 1) {
            g_bar_count = 0;
            __threadfence();
            atomicExch(&g_bar_gen, target);      // release
        } else {
            while (atomicAdd(&g_bar_gen, 0) < target) __nanosleep(64);
        }
    }
    __syncthreads();
}

// ---------------------------------------------------------------------------
// K1: fused graph kernel. sms blocks x 1024 threads, 3 grid barriers.
// ---------------------------------------------------------------------------
__global__ void __launch_bounds__(1024, 1)
graph_kernel(const float4* __restrict__ x4,
             const int* __restrict__ ei,
             const float* __restrict__ W1,
             const float* __restrict__ W2,
             int N, int E, int nChunks) {
    __shared__ int s[1024];
    const int nb   = gridDim.x;
    const int tid  = threadIdx.x;
    const int gtid = blockIdx.x * 1024 + tid;
    const int T    = nb * 1024;

    const int gen0 = atomicAdd(&g_bar_gen, 0);   // read before any barrier

    // ---- P1: weight split + g_base zero + degree hist + rank ----
    if (gtid < DIM * DIM) {
        int k = gtid >> 7, n = gtid & 127;
        int o = n * PA + k;
        __nv_bfloat16 h, l;
        bf16_split(W1[gtid], h, l);
        g_w1h[o] = h; g_w1l[o] = l;
        bf16_split(W2[gtid], h, l);
        g_w2h[o] = h; g_w2l[o] = l;
    }
    if (gtid < 64) g_base[gtid] = 0;
    for (int e = gtid; e < E; e += T)
        g_rank[e] = atomicAdd(&g_deg[ei[E + e]], 1);

    grid_barrier(nb, gen0 + 1);

    // ---- P2: per-chunk scan -> g_exc, chunk bases via atomics ----
    for (int c = blockIdx.x; c < nChunks; c += nb) {
        int idx = c * 1024 + tid;
        int v = (idx < N) ? g_deg[idx] : 0;
        s[tid] = v;
        __syncthreads();
        #pragma unroll
        for (int off = 1; off < 1024; off <<= 1) {
            int t = (tid >= off) ? s[tid - off] : 0;
            __syncthreads();
            s[tid] += t;
            __syncthreads();
        }
        if (idx < N) g_exc[idx] = s[tid] - v;
        if (tid == 1023) {
            int tot = s[1023];
            for (int cc = c + 1; cc < nChunks; cc++)
                atomicAdd(&g_base[cc], tot);
        }
        __syncthreads();
    }

    grid_barrier(nb, gen0 + 2);

    // ---- P3: CSR fill ----
    for (int e = gtid; e < E; e += T) {
        int src = ei[e];
        int dst = ei[E + e];
        g_csr[g_exc[dst] + g_base[dst >> 10] + g_rank[e]] = src;
    }

    grid_barrier(nb, gen0 + 3);

    // ---- P4: gather (warp per node, 4-way unrolled); reset g_deg ----
    {
        const int warps = T >> 5;
        const int gw    = gtid >> 5;
        const int lane  = tid & 31;
        for (int node = gw; node < N; node += warps) {
            int deg = g_deg[node];
            int j   = g_exc[node] + g_base[node >> 10];
            int end = j + deg;

            float4 acc0 = x4[(size_t)node * 32 + lane];
            float4 acc1 = make_float4(0.f, 0.f, 0.f, 0.f);

            for (; j + 3 < end; j += 4) {
                int s0 = g_csr[j];
                int s1 = g_csr[j + 1];
                int s2 = g_csr[j + 2];
                int s3 = g_csr[j + 3];
                float4 a = x4[(size_t)s0 * 32 + lane];
                float4 b = x4[(size_t)s1 * 32 + lane];
                float4 c = x4[(size_t)s2 * 32 + lane];
                float4 d = x4[(size_t)s3 * 32 + lane];
                f4add(acc0, a);
                f4add(acc1, b);
                f4add(acc0, c);
                f4add(acc1, d);
            }
            if (j + 1 < end) {
                int s0 = g_csr[j];
                int s1 = g_csr[j + 1];
                float4 a = x4[(size_t)s0 * 32 + lane];
                float4 b = x4[(size_t)s1 * 32 + lane];
                f4add(acc0, a);
                f4add(acc1, b);
                j += 2;
            }
            if (j < end) {
                float4 a = x4[(size_t)g_csr[j] * 32 + lane];
                f4add(acc0, a);
            }
            f4add(acc0, acc1);
            reinterpret_cast<float4*>(g_agg)[(size_t)node * 32 + lane] = acc0;
            if (lane == 0) g_deg[node] = 0;     // ready for next call
        }
    }
}

// ---------------------------------------------------------------------------
// K2: PERSISTENT HMMA MLP. One block per SM; weights loaded once; loop tiles.
// 256 threads / 8 warps tiled 4(m) x 2(n): warp owns 32x64.
// ---------------------------------------------------------------------------
#define SM_AH   1024
#define SM_AL   (SM_AH  + TBYTES)
#define SM_W1H  (SM_AL  + TBYTES)
#define SM_W1L  (SM_W1H + TBYTES)
#define SM_W2H  (SM_W1L + TBYTES)
#define SM_W2L  (SM_W2H + TBYTES)
#define SM_TOT  (SM_W2L + TBYTES)

// acc layout: acc[im*8 + jn*2 + h][4]
__device__ __forceinline__ void do_gemm(const uint32_t aH[2], const uint32_t aL[2],
                                        uint32_t wH, uint32_t wL,
                                        float (*acc)[4]) {
    #pragma unroll
    for (int k = 0; k < 8; k++) {
        uint32_t ah[2][4], al[2][4];
        #pragma unroll
        for (int im = 0; im < 2; im++) {
            ldmx4(aH[im] + k * 32, ah[im]);
            ldmx4(aL[im] + k * 32, al[im]);
        }
        #pragma unroll
        for (int jn = 0; jn < 4; jn++) {
            uint32_t boff = (uint32_t)(jn * 16 * PA * 2 + k * 32);
            uint32_t bh[4], bl[4];
            ldmx4(wH + boff, bh);
            ldmx4(wL + boff, bl);
            #pragma unroll
            for (int im = 0; im < 2; im++) {
                float* c0 = acc[im * 8 + jn * 2];
                float* c1 = acc[im * 8 + jn * 2 + 1];
                mma16816(c0, ah[im], bh[0], bh[1]);
                mma16816(c0, ah[im], bl[0], bl[1]);
                mma16816(c0, al[im], bh[0], bh[1]);
                mma16816(c1, ah[im], bh[2], bh[3]);
                mma16816(c1, ah[im], bl[2], bl[3]);
                mma16816(c1, al[im], bh[2], bh[3]);
            }
        }
    }
}

__global__ void __launch_bounds__(256, 1)
mlp_hmma_kernel(const float* __restrict__ b1,
                const float* __restrict__ b2,
                float* __restrict__ out, int M, int nTiles) {
    extern __shared__ unsigned char sm[];
    const uint32_t sb = smem_u32(sm);
    const int tid  = threadIdx.x;
    const int w    = tid >> 5;
    const int lane = tid & 31;
    const int wm   = w >> 1;
    const int wn   = w & 1;

    float* b1s = reinterpret_cast<float*>(sm);
    float* b2s = reinterpret_cast<float*>(sm + 512);
    if (tid < DIM) {
        b1s[tid] = b1[tid];
        b2s[tid] = b2[tid];
    }

    // weight tiles: loaded ONCE per persistent block
    {
        const uint4* s1h = reinterpret_cast<const uint4*>(g_w1h);
        const uint4* s1l = reinterpret_cast<const uint4*>(g_w1l);
        const uint4* s2h = reinterpret_cast<const uint4*>(g_w2h);
        const uint4* s2l = reinterpret_cast<const uint4*>(g_w2l);
        uint4* d1h = reinterpret_cast<uint4*>(sm + SM_W1H);
        uint4* d1l = reinterpret_cast<uint4*>(sm + SM_W1L);
        uint4* d2h = reinterpret_cast<uint4*>(sm + SM_W2H);
        uint4* d2l = reinterpret_cast<uint4*>(sm + SM_W2L);
        for (int i = tid; i < TBYTES / 16; i += 256) {
            d1h[i] = s1h[i]; d1l[i] = s1l[i];
            d2h[i] = s2h[i]; d2l[i] = s2l[i];
        }
    }

    uint32_t aH[2], aL[2];
    #pragma unroll
    for (int im = 0; im < 2; im++) {
        uint32_t off = (uint32_t)(((wm * 32 + im * 16 + (lane & 15)) * PA
                                   + ((lane >> 4) << 3)) * 2);
        aH[im] = sb + SM_AH + off;
        aL[im] = sb + SM_AL + off;
    }
    const uint32_t bLaneOff =
        (uint32_t)((((lane & 7) + ((lane >> 4) << 3) + wn * 64) * PA
                    + (((lane >> 3) & 1) << 3)) * 2);
    const uint32_t w1H = sb + SM_W1H + bLaneOff;
    const uint32_t w1L = sb + SM_W1L + bLaneOff;
    const uint32_t w2H = sb + SM_W2H + bLaneOff;
    const uint32_t w2L = sb + SM_W2L + bLaneOff;

    for (int t = blockIdx.x; t < nTiles; t += gridDim.x) {
        const int rowBase = t * TILE_M;

        __syncthreads();   // prior tile's GEMM2 reads of Ah/Al must be done

        // A tile: load agg rows, split bf16 hi/lo, [m][k] pitch PA
        {
            __nv_bfloat16* Ah = reinterpret_cast<__nv_bfloat16*>(sm + SM_AH);
            __nv_bfloat16* Al = reinterpret_cast<__nv_bfloat16*>(sm + SM_AL);
            const float4* in4 = reinterpret_cast<const float4*>(g_agg);
            #pragma unroll
            for (int i = tid; i < TILE_M * 32; i += 256) {
                int m = i >> 5, c = i & 31;
                int gm = rowBase + m;
                float4 v = make_float4(0.f, 0.f, 0.f, 0.f);
                if (gm < M) v = in4[(size_t)gm * 32 + c];
                float vv[4] = {v.x, v.y, v.z, v.w};
                #pragma unroll
                for (int j = 0; j < 4; j++) {
                    __nv_bfloat16 h, l;
                    bf16_split(vv[j], h, l);
                    Ah[m * PA + c * 4 + j] = h;
                    Al[m * PA + c * 4 + j] = l;
                }
            }
        }
        __syncthreads();

        float acc[16][4];
        #pragma unroll
        for (int i = 0; i < 16; i++)
            #pragma unroll
            for (int j = 0; j < 4; j++) acc[i][j] = 0.f;

        // ---- GEMM1 ----
        do_gemm(aH, aL, w1H, w1L, acc);

        // ---- epilogue 1: +b1, relu, split -> H into Ah/Al ----
        {
            __nv_bfloat16* Ah = reinterpret_cast<__nv_bfloat16*>(sm + SM_AH);
            __nv_bfloat16* Al = reinterpret_cast<__nv_bfloat16*>(sm + SM_AL);
            #pragma unroll
            for (int im = 0; im < 2; im++) {
                int r0 = wm * 32 + im * 16 + (lane >> 2);
                int r1 = r0 + 8;
                #pragma unroll
                for (int jn = 0; jn < 4; jn++) {
                    #pragma unroll
                    for (int h = 0; h < 2; h++) {
                        float* c = acc[im * 8 + jn * 2 + h];
                        int n = wn * 64 + jn * 16 + h * 8 + 2 * (lane & 3);
                        float f00 = c[0] + b1s[n];
                        float f01 = c[1] + b1s[n + 1];
                        float f10 = c[2] + b1s[n];
                        float f11 = c[3] + b1s[n + 1];
                        f00 = f00 > 0.f ? f00 : 0.f;  f01 = f01 > 0.f ? f01 : 0.f;
                        f10 = f10 > 0.f ? f10 : 0.f;  f11 = f11 > 0.f ? f11 : 0.f;
                        __nv_bfloat16 hh, ll;
                        bf16_split(f00, hh, ll); Ah[r0*PA + n]   = hh; Al[r0*PA + n]   = ll;
                        bf16_split(f01, hh, ll); Ah[r0*PA + n+1] = hh; Al[r0*PA + n+1] = ll;
                        bf16_split(f10, hh, ll); Ah[r1*PA + n]   = hh; Al[r1*PA + n]   = ll;
                        bf16_split(f11, hh, ll); Ah[r1*PA + n+1] = hh; Al[r1*PA + n+1] = ll;
                        c[0] = c[1] = c[2] = c[3] = 0.f;
                    }
                }
            }
        }
        __syncthreads();

        // ---- GEMM2 ----
        do_gemm(aH, aL, w2H, w2L, acc);

        // ---- epilogue 2: +b2, store fp32 ----
        #pragma unroll
        for (int im = 0; im < 2; im++) {
            int gm0 = rowBase + wm * 32 + im * 16 + (lane >> 2);
            int gm1 = gm0 + 8;
            #pragma unroll
            for (int jn = 0; jn < 4; jn++) {
                #pragma unroll
                for (int h = 0; h < 2; h++) {
                    float* c = acc[im * 8 + jn * 2 + h];
                    int n = wn * 64 + jn * 16 + h * 8 + 2 * (lane & 3);
                    if (gm0 < M) {
                        float2 o = make_float2(c[0] + b2s[n], c[1] + b2s[n + 1]);
                        *reinterpret_cast<float2*>(&out[(size_t)gm0 * DIM + n]) = o;
                    }
                    if (gm1 < M) {
                        float2 o = make_float2(c[2] + b2s[n], c[3] + b2s[n + 1]);
                        *reinterpret_cast<float2*>(&out[(size_t)gm1 * DIM + n]) = o;
                    }
                }
            }
        }
    }
}

// ---------------------------------------------------------------------------
// launch
// ---------------------------------------------------------------------------
extern "C" void kernel_launch(void* const* d_in, const int* in_sizes, int n_in,
                              void* d_out, int out_size) {
    const float* x   = (const float*)d_in[0];
    const int*   ei  = (const int*)d_in[1];
    const float* W1  = (const float*)d_in[2];
    const float* b1  = (const float*)d_in[3];
    const float* W2  = (const float*)d_in[4];
    const float* b2  = (const float*)d_in[5];
    float*       out = (float*)d_out;

    const int M = in_sizes[0] / DIM;   // 50000
    const int E = in_sizes[1] / 2;     // 640000
    const int nChunks = (M + 1023) / 1024;
    const int nTiles  = (M + TILE_M - 1) / TILE_M;

    int sms = 148;
    cudaDeviceGetAttribute(&sms, cudaDevAttrMultiProcessorCount, 0);

    // K1: fused graph phase (guaranteed co-resident: grid == SM count)
    graph_kernel<<<sms, 1024>>>(
        reinterpret_cast<const float4*>(x), ei, W1, W2, M, E, nChunks);

    // K2: persistent MLP
    int grid = sms < nTiles ? sms : nTiles;
    cudaFuncSetAttribute(mlp_hmma_kernel,
                         cudaFuncAttributeMaxDynamicSharedMemorySize, SM_TOT);
    mlp_hmma_kernel<<<grid, 256, SM_TOT>>>(b1, b2, out, M, nTiles);
}

// round 17
// speedup vs baseline: 2.2888x; 2.2888x over previous
#include <cuda_runtime.h>
#include <cuda_bf16.h>
#include <cstdint>

// ---------------------------------------------------------------------------
// GINConv: out = relu((x + segment_sum(x[src], dst)) @ W1 + b1) @ W2 + b2
// N=50000, E=640000, D=128, fp32, edge_index int32. 5 launches.
// (R16 showed grid-barrier fusion of the graph phase regresses 2x: keep the
//  5-launch structure. R10 showed gather must not live inside the MLP.)
//
//   K1: hist   - deg histogram + per-edge rank, 4 edges/thread
//   K2: scan1  - per-chunk scan -> g_exc; chunk bases via atomics to g_base
//   K3: fill   - CSR fill, 4 edges/thread
//   K4: gather - agg = x + sum x[csr] (plateau ~28us, LTS-cap bound)
//   K5: mlp    - PERSISTENT HMMA bf16x3, 512 thr / 16 warps, 8(m)x2(n);
//                ~75 regs/thr (R7's "spill" was misattributed - real culprit
//                was scan_single, proven in R8)
// ---------------------------------------------------------------------------

#define DIM    128
#define MAX_N  50000
#define MAX_E  640000
#define TILE_M 128
#define PA     136                       // padded pitch (elems), 272B rows
#define TBYTES (128 * PA * 2)            // 34816 B per bf16 tile

__device__ float g_agg[MAX_N * DIM];

__device__ int g_deg[MAX_N];             // zero-init at load; gather resets
__device__ int g_exc[MAX_N];
__device__ int g_base[64];
__device__ int g_rank[MAX_E];
__device__ int g_csr[MAX_E];

// W^T hi/lo tiles, [n][k] row-major, pitch PA
__device__ __align__(16) __nv_bfloat16 g_w1h[128 * PA];
__device__ __align__(16) __nv_bfloat16 g_w1l[128 * PA];
__device__ __align__(16) __nv_bfloat16 g_w2h[128 * PA];
__device__ __align__(16) __nv_bfloat16 g_w2l[128 * PA];

__device__ __forceinline__ uint32_t smem_u32(const void* p) {
    uint32_t a;
    asm("{ .reg .u64 t; cvta.to.shared.u64 t, %1; cvt.u32.u64 %0, t; }"
        : "=r"(a) : "l"(p));
    return a;
}
__device__ __forceinline__ void ldmx4(uint32_t addr, uint32_t r[4]) {
    asm volatile("ldmatrix.sync.aligned.m8n8.x4.shared.b16 {%0,%1,%2,%3}, [%4];"
                 : "=r"(r[0]), "=r"(r[1]), "=r"(r[2]), "=r"(r[3]) : "r"(addr));
}
__device__ __forceinline__ void mma16816(float c[4], const uint32_t a[4],
                                         uint32_t b0, uint32_t b1) {
    asm volatile("mma.sync.aligned.m16n8k16.row.col.f32.bf16.bf16.f32 "
                 "{%0,%1,%2,%3}, {%4,%5,%6,%7}, {%8,%9}, {%0,%1,%2,%3};"
                 : "+f"(c[0]), "+f"(c[1]), "+f"(c[2]), "+f"(c[3])
                 : "r"(a[0]), "r"(a[1]), "r"(a[2]), "r"(a[3]), "r"(b0), "r"(b1));
}
__device__ __forceinline__ void bf16_split(float a, __nv_bfloat16& h, __nv_bfloat16& l) {
    h = __float2bfloat16_rn(a);
    l = __float2bfloat16_rn(a - __bfloat162float(h));
}
__device__ __forceinline__ void f4add(float4& a, const float4 b) {
    a.x += b.x; a.y += b.y; a.z += b.z; a.w += b.w;
}

// ---------------------------------------------------------------------------
// K1: hist + weight prep + g_base zero. 4 edges/thread.
// ---------------------------------------------------------------------------
__global__ void hist_kernel(const int* __restrict__ ei, int E,
                            const float* __restrict__ W1,
                            const float* __restrict__ W2) {
    int base = blockIdx.x * 1024 + threadIdx.x;
    int t    = blockIdx.x * 256 + threadIdx.x;

    if (t < DIM * DIM) {
        int k = t >> 7, n = t & 127;
        int o = n * PA + k;
        __nv_bfloat16 h, l;
        bf16_split(W1[t], h, l);
        g_w1h[o] = h; g_w1l[o] = l;
        bf16_split(W2[t], h, l);
        g_w2h[o] = h; g_w2l[o] = l;
    }
    if (t < 64) g_base[t] = 0;

    int d0 = -1, d1 = -1, d2 = -1, d3 = -1;
    int e0 = base, e1 = base + 256, e2 = base + 512, e3 = base + 768;
    if (e0 < E) d0 = ei[E + e0];
    if (e1 < E) d1 = ei[E + e1];
    if (e2 < E) d2 = ei[E + e2];
    if (e3 < E) d3 = ei[E + e3];
    if (d0 >= 0) g_rank[e0] = atomicAdd(&g_deg[d0], 1);
    if (d1 >= 0) g_rank[e1] = atomicAdd(&g_deg[d1], 1);
    if (d2 >= 0) g_rank[e2] = atomicAdd(&g_deg[d2], 1);
    if (d3 >= 0) g_rank[e3] = atomicAdd(&g_deg[d3], 1);
}

// ---------------------------------------------------------------------------
// K2: per-chunk scan -> g_exc; chunk totals broadcast via atomics to g_base
// ---------------------------------------------------------------------------
__global__ void scan1_kernel(int N, int nChunks) {
    __shared__ int s[1024];
    int tid = threadIdx.x;
    int idx = blockIdx.x * 1024 + tid;
    int v = (idx < N) ? g_deg[idx] : 0;
    s[tid] = v;
    __syncthreads();
    #pragma unroll
    for (int off = 1; off < 1024; off <<= 1) {
        int t = (tid >= off) ? s[tid - off] : 0;
        __syncthreads();
        s[tid] += t;
        __syncthreads();
    }
    if (idx < N) g_exc[idx] = s[tid] - v;          // exclusive within chunk
    if (tid == 1023) {
        int tot = s[1023];
        for (int c = blockIdx.x + 1; c < nChunks; c++)
            atomicAdd(&g_base[c], tot);
    }
}

// ---------------------------------------------------------------------------
// K3: CSR fill, 4 edges/thread
// ---------------------------------------------------------------------------
__global__ void fill_kernel(const int* __restrict__ ei, int E) {
    int base = blockIdx.x * 1024 + threadIdx.x;

    int e[4], src[4], dst[4];
    bool ok[4];
    #pragma unroll
    for (int q = 0; q < 4; q++) {
        e[q]  = base + q * 256;
        ok[q] = e[q] < E;
        src[q] = ok[q] ? ei[e[q]]     : 0;
        dst[q] = ok[q] ? ei[E + e[q]] : 0;
    }
    int pos[4];
    #pragma unroll
    for (int q = 0; q < 4; q++)
        pos[q] = ok[q] ? (g_exc[dst[q]] + g_base[dst[q] >> 10] + g_rank[e[q]]) : 0;
    #pragma unroll
    for (int q = 0; q < 4; q++)
        if (ok[q]) g_csr[pos[q]] = src[q];
}

// ---------------------------------------------------------------------------
// K4: gather-sum, warp per node, 4-way unrolled; resets g_deg
// ---------------------------------------------------------------------------
__global__ void gather_kernel(const float4* __restrict__ x4, int N) {
    int node = blockIdx.x * 8 + (threadIdx.x >> 5);
    int lane = threadIdx.x & 31;
    if (node >= N) return;

    int deg = g_deg[node];
    int j   = g_exc[node] + g_base[node >> 10];
    int end = j + deg;

    float4 acc0 = x4[(size_t)node * 32 + lane];
    float4 acc1 = make_float4(0.f, 0.f, 0.f, 0.f);

    for (; j + 3 < end; j += 4) {
        int s0 = g_csr[j];
        int s1 = g_csr[j + 1];
        int s2 = g_csr[j + 2];
        int s3 = g_csr[j + 3];
        float4 a = x4[(size_t)s0 * 32 + lane];
        float4 b = x4[(size_t)s1 * 32 + lane];
        float4 c = x4[(size_t)s2 * 32 + lane];
        float4 d = x4[(size_t)s3 * 32 + lane];
        f4add(acc0, a);
        f4add(acc1, b);
        f4add(acc0, c);
        f4add(acc1, d);
    }
    if (j + 1 < end) {
        int s0 = g_csr[j];
        int s1 = g_csr[j + 1];
        float4 a = x4[(size_t)s0 * 32 + lane];
        float4 b = x4[(size_t)s1 * 32 + lane];
        f4add(acc0, a);
        f4add(acc1, b);
        j += 2;
    }
    if (j < end) {
        float4 a = x4[(size_t)g_csr[j] * 32 + lane];
        f4add(acc0, a);
    }
    f4add(acc0, acc1);
    reinterpret_cast<float4*>(g_agg)[(size_t)node * 32 + lane] = acc0;
    if (lane == 0) g_deg[node] = 0;     // ready for next call's hist
}

// ---------------------------------------------------------------------------
// K5: PERSISTENT HMMA MLP. 512 threads / 16 warps tiled 8(m) x 2(n):
// warp owns 16 rows x 64 cols (acc[8][4] = 32 regs; ~75 regs total).
// smem: b1s | b2s | Ah | Al | W1h | W1l | W2h | W2l
// ---------------------------------------------------------------------------
#define SM_AH   1024
#define SM_AL   (SM_AH  + TBYTES)
#define SM_W1H  (SM_AL  + TBYTES)
#define SM_W1L  (SM_W1H + TBYTES)
#define SM_W2H  (SM_W1L + TBYTES)
#define SM_W2L  (SM_W2H + TBYTES)
#define SM_TOT  (SM_W2L + TBYTES)

// acc[jn*2 + h][4], jn in 0..3, h = n8 half
__device__ __forceinline__ void do_gemm(uint32_t aH, uint32_t aL,
                                        uint32_t wH, uint32_t wL,
                                        float (*acc)[4]) {
    #pragma unroll
    for (int k = 0; k < 8; k++) {
        uint32_t ah[4], al[4];
        ldmx4(aH + k * 32, ah);
        ldmx4(aL + k * 32, al);
        #pragma unroll
        for (int jn = 0; jn < 4; jn++) {
            uint32_t boff = (uint32_t)(jn * 16 * PA * 2 + k * 32);
            uint32_t bh[4], bl[4];
            ldmx4(wH + boff, bh);
            ldmx4(wL + boff, bl);
            float* c0 = acc[jn * 2];
            float* c1 = acc[jn * 2 + 1];
            mma16816(c0, ah, bh[0], bh[1]);
            mma16816(c0, ah, bl[0], bl[1]);
            mma16816(c0, al, bh[0], bh[1]);
            mma16816(c1, ah, bh[2], bh[3]);
            mma16816(c1, ah, bl[2], bl[3]);
            mma16816(c1, al, bh[2], bh[3]);
        }
    }
}

__global__ void __launch_bounds__(512, 1)
mlp_hmma_kernel(const float* __restrict__ b1,
                const float* __restrict__ b2,
                float* __restrict__ out, int M, int nTiles) {
    extern __shared__ unsigned char sm[];
    const uint32_t sb = smem_u32(sm);
    const int tid  = threadIdx.x;
    const int w    = tid >> 5;
    const int lane = tid & 31;
    const int wm   = w >> 1;          // 0..7: rows [16wm, 16wm+16)
    const int wn   = w & 1;           // 0..1: cols [64wn, 64wn+64)

    float* b1s = reinterpret_cast<float*>(sm);
    float* b2s = reinterpret_cast<float*>(sm + 512);
    if (tid < DIM) {
        b1s[tid] = b1[tid];
        b2s[tid] = b2[tid];
    }

    // weight tiles: loaded ONCE per persistent block
    {
        const uint4* s1h = reinterpret_cast<const uint4*>(g_w1h);
        const uint4* s1l = reinterpret_cast<const uint4*>(g_w1l);
        const uint4* s2h = reinterpret_cast<const uint4*>(g_w2h);
        const uint4* s2l = reinterpret_cast<const uint4*>(g_w2l);
        uint4* d1h = reinterpret_cast<uint4*>(sm + SM_W1H);
        uint4* d1l = reinterpret_cast<uint4*>(sm + SM_W1L);
        uint4* d2h = reinterpret_cast<uint4*>(sm + SM_W2H);
        uint4* d2l = reinterpret_cast<uint4*>(sm + SM_W2L);
        for (int i = tid; i < TBYTES / 16; i += 512) {
            d1h[i] = s1h[i]; d1l[i] = s1l[i];
            d2h[i] = s2h[i]; d2l[i] = s2l[i];
        }
    }

    // fixed ldmatrix lane addressing
    // A m16k16: row = 16*wm + (lane&15), col-half = (lane>>4)*8
    const uint32_t aLaneOff =
        (uint32_t)(((wm * 16 + (lane & 15)) * PA + ((lane >> 4) << 3)) * 2);
    const uint32_t aH = sb + SM_AH + aLaneOff;
    const uint32_t aL = sb + SM_AL + aLaneOff;
    // B n16k16: row = (lane&7)+((lane>>4)<<3)+64*wn, col = ((lane>>3)&1)<<3
    const uint32_t bLaneOff =
        (uint32_t)((((lane & 7) + ((lane >> 4) << 3) + wn * 64) * PA
                    + (((lane >> 3) & 1) << 3)) * 2);
    const uint32_t w1H = sb + SM_W1H + bLaneOff;
    const uint32_t w1L = sb + SM_W1L + bLaneOff;
    const uint32_t w2H = sb + SM_W2H + bLaneOff;
    const uint32_t w2L = sb + SM_W2L + bLaneOff;

    for (int t = blockIdx.x; t < nTiles; t += gridDim.x) {
        const int rowBase = t * TILE_M;

        __syncthreads();   // prior tile's GEMM2 reads of Ah/Al must be done

        // A tile: load agg rows, split bf16 hi/lo, [m][k] pitch PA
        {
            __nv_bfloat16* Ah = reinterpret_cast<__nv_bfloat16*>(sm + SM_AH);
            __nv_bfloat16* Al = reinterpret_cast<__nv_bfloat16*>(sm + SM_AL);
            const float4* in4 = reinterpret_cast<const float4*>(g_agg);
            #pragma unroll
            for (int i = tid; i < TILE_M * 32; i += 512) {
                int m = i >> 5, c = i & 31;
                int gm = rowBase + m;
                float4 v = make_float4(0.f, 0.f, 0.f, 0.f);
                if (gm < M) v = in4[(size_t)gm * 32 + c];
                float vv[4] = {v.x, v.y, v.z, v.w};
                #pragma unroll
                for (int j = 0; j < 4; j++) {
                    __nv_bfloat16 h, l;
                    bf16_split(vv[j], h, l);
                    Ah[m * PA + c * 4 + j] = h;
                    Al[m * PA + c * 4 + j] = l;
                }
            }
        }
        __syncthreads();

        float acc[8][4];
        #pragma unroll
        for (int i = 0; i < 8; i++)
            #pragma unroll
            for (int j = 0; j < 4; j++) acc[i][j] = 0.f;

        // ---- GEMM1 ----
        do_gemm(aH, aL, w1H, w1L, acc);

        // ---- epilogue 1: +b1, relu, split -> H into Ah/Al ----
        {
            __nv_bfloat16* Ah = reinterpret_cast<__nv_bfloat16*>(sm + SM_AH);
            __nv_bfloat16* Al = reinterpret_cast<__nv_bfloat16*>(sm + SM_AL);
            int r0 = wm * 16 + (lane >> 2);
            int r1 = r0 + 8;
            #pragma unroll
            for (int jn = 0; jn < 4; jn++) {
                #pragma unroll
                for (int h = 0; h < 2; h++) {
                    float* c = acc[jn * 2 + h];
                    int n = wn * 64 + jn * 16 + h * 8 + 2 * (lane & 3);
                    float f00 = c[0] + b1s[n];
                    float f01 = c[1] + b1s[n + 1];
                    float f10 = c[2] + b1s[n];
                    float f11 = c[3] + b1s[n + 1];
                    f00 = f00 > 0.f ? f00 : 0.f;  f01 = f01 > 0.f ? f01 : 0.f;
                    f10 = f10 > 0.f ? f10 : 0.f;  f11 = f11 > 0.f ? f11 : 0.f;
                    __nv_bfloat16 hh, ll;
                    bf16_split(f00, hh, ll); Ah[r0*PA + n]   = hh; Al[r0*PA + n]   = ll;
                    bf16_split(f01, hh, ll); Ah[r0*PA + n+1] = hh; Al[r0*PA + n+1] = ll;
                    bf16_split(f10, hh, ll); Ah[r1*PA + n]   = hh; Al[r1*PA + n]   = ll;
                    bf16_split(f11, hh, ll); Ah[r1*PA + n+1] = hh; Al[r1*PA + n+1] = ll;
                    c[0] = c[1] = c[2] = c[3] = 0.f;
                }
            }
        }
        __syncthreads();   // H cols of a row written by both n-warps

        // ---- GEMM2 ----
        do_gemm(aH, aL, w2H, w2L, acc);

        // ---- epilogue 2: +b2, store fp32 ----
        {
            int gm0 = rowBase + wm * 16 + (lane >> 2);
            int gm1 = gm0 + 8;
            #pragma unroll
            for (int jn = 0; jn < 4; jn++) {
                #pragma unroll
                for (int h = 0; h < 2; h++) {
                    float* c = acc[jn * 2 + h];
                    int n = wn * 64 + jn * 16 + h * 8 + 2 * (lane & 3);
                    if (gm0 < M) {
                        float2 o = make_float2(c[0] + b2s[n], c[1] + b2s[n + 1]);
                        *reinterpret_cast<float2*>(&out[(size_t)gm0 * DIM + n]) = o;
                    }
                    if (gm1 < M) {
                        float2 o = make_float2(c[2] + b2s[n], c[3] + b2s[n + 1]);
                        *reinterpret_cast<float2*>(&out[(size_t)gm1 * DIM + n]) = o;
                    }
                }
            }
        }
    }
}

// ---------------------------------------------------------------------------
// launch
// ---------------------------------------------------------------------------
extern "C" void kernel_launch(void* const* d_in, const int* in_sizes, int n_in,
                              void* d_out, int out_size) {
    const float* x   = (const float*)d_in[0];
    const int*   ei  = (const int*)d_in[1];
    const float* W1  = (const float*)d_in[2];
    const float* b1  = (const float*)d_in[3];
    const float* W2  = (const float*)d_in[4];
    const float* b2  = (const float*)d_in[5];
    float*       out = (float*)d_out;

    const int M = in_sizes[0] / DIM;   // 50000
    const int E = in_sizes[1] / 2;     // 640000
    const int nChunks = (M + 1023) / 1024;
    const int nTiles  = (M + TILE_M - 1) / TILE_M;
    const int eBlocks = (E + 1023) / 1024;   // 4 edges/thread

    hist_kernel<<<eBlocks, 256>>>(ei, E, W1, W2);
    scan1_kernel<<<nChunks, 1024>>>(M, nChunks);
    fill_kernel<<<eBlocks, 256>>>(ei, E);
    gather_kernel<<<(M + 7) / 8, 256>>>(
        reinterpret_cast<const float4*>(x), M);

    int sms = 148;
    cudaDeviceGetAttribute(&sms, cudaDevAttrMultiProcessorCount, 0);
    int grid = sms < nTiles ? sms : nTiles;

    cudaFuncSetAttribute(mlp_hmma_kernel,
                         cudaFuncAttributeMaxDynamicSharedMemorySize, SM_TOT);
    mlp_hmma_kernel<<<grid, 512, SM_TOT>>>(b1, b2, out, M, nTiles);
}